// round 10
// baseline (speedup 1.0000x reference)
#include <cuda_runtime.h>
#include <math.h>

#define B_ 4096
#define D_ 512
#define H_ 8

// Scratch (allocation-free: device globals)
__device__ float g_x[B_ * D_];   // layernormed input
__device__ float g_q[B_ * D_];
__device__ float g_k[B_ * D_];
__device__ float g_v[B_ * D_];
__device__ float g_ao[B_ * D_];  // attention output

// ---------------------------------------------------------------------------
// LayerNorm: one CTA (128 threads) per row of 512 floats (float4 per thread)
// ---------------------------------------------------------------------------
__global__ __launch_bounds__(128) void ln_kernel(const float* __restrict__ in,
                                                 const float* __restrict__ w,
                                                 const float* __restrict__ b) {
    int row = blockIdx.x;
    int t = threadIdx.x;
    float4 v = ((const float4*)(in + row * D_))[t];
    float s  = v.x + v.y + v.z + v.w;
    float sq = v.x * v.x + v.y * v.y + v.z * v.z + v.w * v.w;
#pragma unroll
    for (int d = 16; d > 0; d >>= 1) {
        s  += __shfl_xor_sync(0xffffffffu, s, d);
        sq += __shfl_xor_sync(0xffffffffu, sq, d);
    }
    __shared__ float ss[4], ssq[4];
    if ((t & 31) == 0) { ss[t >> 5] = s; ssq[t >> 5] = sq; }
    __syncthreads();
    s  = ss[0] + ss[1] + ss[2] + ss[3];
    sq = ssq[0] + ssq[1] + ssq[2] + ssq[3];
    float mu   = s * (1.0f / D_);
    float var  = fmaxf(sq * (1.0f / D_) - mu * mu, 0.0f);
    float rstd = rsqrtf(var + 1e-5f);
    float4 wv = ((const float4*)w)[t];
    float4 bv = ((const float4*)b)[t];
    float4 o;
    o.x = (v.x - mu) * rstd * wv.x + bv.x;
    o.y = (v.y - mu) * rstd * wv.y + bv.y;
    o.z = (v.z - mu) * rstd * wv.z + bv.z;
    o.w = (v.w - mu) * rstd * wv.w + bv.w;
    ((float4*)(g_x + row * D_))[t] = o;
}

// ---------------------------------------------------------------------------
// QKV GEMM: C[m,n] = sum_k X[m,k] * W[n,k]   (64x64 tiles, 4x4/thread strided)
// blockIdx.z selects q/k/v
// ---------------------------------------------------------------------------
__global__ __launch_bounds__(256) void qkv_gemm(const float* __restrict__ Wq,
                                                const float* __restrict__ Wk,
                                                const float* __restrict__ Wv) {
    __shared__ float As[64 * 68];
    __shared__ float Bs[64 * 68];
    const float* W = (blockIdx.z == 0) ? Wq : ((blockIdx.z == 1) ? Wk : Wv);
    float* C = (blockIdx.z == 0) ? g_q : ((blockIdx.z == 1) ? g_k : g_v);
    int tid = threadIdx.x;
    int ty = tid >> 4, tx = tid & 15;
    int m0 = blockIdx.x * 64, n0 = blockIdx.y * 64;
    int lr = tid >> 4, lc = (tid & 15) * 4;
    float acc[4][4] = {};
    for (int k0 = 0; k0 < D_; k0 += 64) {
#pragma unroll
        for (int r = 0; r < 64; r += 16) {
            *(float4*)&As[(lr + r) * 68 + lc] = *(const float4*)&g_x[(m0 + lr + r) * D_ + k0 + lc];
            *(float4*)&Bs[(lr + r) * 68 + lc] = *(const float4*)&W[(n0 + lr + r) * D_ + k0 + lc];
        }
        __syncthreads();
#pragma unroll 16
        for (int kk = 0; kk < 64; kk++) {
            float a[4], b[4];
#pragma unroll
            for (int i = 0; i < 4; i++) a[i] = As[(ty + 16 * i) * 68 + kk];
#pragma unroll
            for (int j = 0; j < 4; j++) b[j] = Bs[(tx + 16 * j) * 68 + kk];
#pragma unroll
            for (int i = 0; i < 4; i++)
#pragma unroll
                for (int j = 0; j < 4; j++) acc[i][j] += a[i] * b[j];
        }
        __syncthreads();
    }
#pragma unroll
    for (int i = 0; i < 4; i++)
#pragma unroll
        for (int j = 0; j < 4; j++)
            C[(m0 + ty + 16 * i) * D_ + n0 + tx + 16 * j] = acc[i][j];
}

// ---------------------------------------------------------------------------
// Flash attention, fp32, per (64-query-block, head). BM=BN=DH=64.
// S = (Q K^T)/sqrt(512); leaky_relu(0.2); online softmax; O += P V.
// ---------------------------------------------------------------------------
__global__ __launch_bounds__(256) void attn_kernel() {
    extern __shared__ float smbuf[];
    float* Qs = smbuf;                 // [64][68]
    float* Ks = smbuf + 64 * 68;
    float* Vs = smbuf + 2 * 64 * 68;
    float* Ps = smbuf + 3 * 64 * 68;
    int h  = blockIdx.y;
    int m0 = blockIdx.x * 64;
    int tid = threadIdx.x;
    int ty = tid >> 4, tx = tid & 15;
    int lr = tid >> 4, lc = (tid & 15) * 4;
    const float invt = 0.044194173824159216f;  // 1/sqrt(512)

#pragma unroll
    for (int r = 0; r < 64; r += 16) {
        float4 q = *(const float4*)&g_q[(m0 + lr + r) * D_ + h * 64 + lc];
        q.x *= invt; q.y *= invt; q.z *= invt; q.w *= invt;
        *(float4*)&Qs[(lr + r) * 68 + lc] = q;
    }

    float m_i[4], l_i[4], o[4][4];
#pragma unroll
    for (int i = 0; i < 4; i++) {
        m_i[i] = -1e30f; l_i[i] = 0.0f;
#pragma unroll
        for (int j = 0; j < 4; j++) o[i][j] = 0.0f;
    }

    for (int nb = 0; nb < 64; nb++) {
        int n0 = nb * 64;
#pragma unroll
        for (int r = 0; r < 64; r += 16) {
            *(float4*)&Ks[(lr + r) * 68 + lc] = *(const float4*)&g_k[(n0 + lr + r) * D_ + h * 64 + lc];
            *(float4*)&Vs[(lr + r) * 68 + lc] = *(const float4*)&g_v[(n0 + lr + r) * D_ + h * 64 + lc];
        }
        __syncthreads();

        float s[4][4] = {};
#pragma unroll 16
        for (int kk = 0; kk < 64; kk++) {
            float a[4], b[4];
#pragma unroll
            for (int i = 0; i < 4; i++) a[i] = Qs[(ty + 16 * i) * 68 + kk];
#pragma unroll
            for (int j = 0; j < 4; j++) b[j] = Ks[(tx + 16 * j) * 68 + kk];
#pragma unroll
            for (int i = 0; i < 4; i++)
#pragma unroll
                for (int j = 0; j < 4; j++) s[i][j] += a[i] * b[j];
        }
        // leaky relu (scale 1/temp already folded into Q)
#pragma unroll
        for (int i = 0; i < 4; i++)
#pragma unroll
            for (int j = 0; j < 4; j++) {
                float z = s[i][j];
                s[i][j] = (z >= 0.0f) ? z : 0.2f * z;
            }
        // row max across the 16 tx-threads (lanes 0-15 / 16-31 of warp)
        float rm[4], alpha[4], rs[4];
#pragma unroll
        for (int i = 0; i < 4; i++)
            rm[i] = fmaxf(fmaxf(s[i][0], s[i][1]), fmaxf(s[i][2], s[i][3]));
#pragma unroll
        for (int d = 8; d > 0; d >>= 1)
#pragma unroll
            for (int i = 0; i < 4; i++)
                rm[i] = fmaxf(rm[i], __shfl_xor_sync(0xffffffffu, rm[i], d, 16));
#pragma unroll
        for (int i = 0; i < 4; i++) {
            float mn = fmaxf(m_i[i], rm[i]);
            alpha[i] = __expf(m_i[i] - mn);
            m_i[i] = mn;
            rs[i] = 0.0f;
        }
#pragma unroll
        for (int i = 0; i < 4; i++)
#pragma unroll
            for (int j = 0; j < 4; j++) {
                float p = __expf(s[i][j] - m_i[i]);
                Ps[(ty + 16 * i) * 68 + tx + 16 * j] = p;
                rs[i] += p;
            }
#pragma unroll
        for (int d = 8; d > 0; d >>= 1)
#pragma unroll
            for (int i = 0; i < 4; i++)
                rs[i] += __shfl_xor_sync(0xffffffffu, rs[i], d, 16);
#pragma unroll
        for (int i = 0; i < 4; i++) {
            l_i[i] = l_i[i] * alpha[i] + rs[i];
#pragma unroll
            for (int j = 0; j < 4; j++) o[i][j] *= alpha[i];
        }
        __syncthreads();  // Ps visible

#pragma unroll 16
        for (int kk = 0; kk < 64; kk++) {
            float p[4], vv[4];
#pragma unroll
            for (int i = 0; i < 4; i++) p[i] = Ps[(ty + 16 * i) * 68 + kk];
#pragma unroll
            for (int j = 0; j < 4; j++) vv[j] = Vs[kk * 68 + tx + 16 * j];
#pragma unroll
            for (int i = 0; i < 4; i++)
#pragma unroll
                for (int j = 0; j < 4; j++) o[i][j] += p[i] * vv[j];
        }
        __syncthreads();  // done with Ks/Vs/Ps before next-iter overwrite
    }

#pragma unroll
    for (int i = 0; i < 4; i++) {
        float inv = 1.0f / l_i[i];
#pragma unroll
        for (int j = 0; j < 4; j++)
            g_ao[(m0 + ty + 16 * i) * D_ + h * 64 + tx + 16 * j] = o[i][j] * inv;
    }
}

// ---------------------------------------------------------------------------
// FC GEMM + bias + residual: out = g_ao @ fc_w^T + fc_b + in_feats
// ---------------------------------------------------------------------------
__global__ __launch_bounds__(256) void fc_gemm(const float* __restrict__ W,
                                               const float* __restrict__ bias,
                                               const float* __restrict__ skip,
                                               float* __restrict__ out) {
    __shared__ float As[64 * 68];
    __shared__ float Bs[64 * 68];
    int tid = threadIdx.x;
    int ty = tid >> 4, tx = tid & 15;
    int m0 = blockIdx.x * 64, n0 = blockIdx.y * 64;
    int lr = tid >> 4, lc = (tid & 15) * 4;
    float acc[4][4] = {};
    for (int k0 = 0; k0 < D_; k0 += 64) {
#pragma unroll
        for (int r = 0; r < 64; r += 16) {
            *(float4*)&As[(lr + r) * 68 + lc] = *(const float4*)&g_ao[(m0 + lr + r) * D_ + k0 + lc];
            *(float4*)&Bs[(lr + r) * 68 + lc] = *(const float4*)&W[(n0 + lr + r) * D_ + k0 + lc];
        }
        __syncthreads();
#pragma unroll 16
        for (int kk = 0; kk < 64; kk++) {
            float a[4], b[4];
#pragma unroll
            for (int i = 0; i < 4; i++) a[i] = As[(ty + 16 * i) * 68 + kk];
#pragma unroll
            for (int j = 0; j < 4; j++) b[j] = Bs[(tx + 16 * j) * 68 + kk];
#pragma unroll
            for (int i = 0; i < 4; i++)
#pragma unroll
                for (int j = 0; j < 4; j++) acc[i][j] += a[i] * b[j];
        }
        __syncthreads();
    }
#pragma unroll
    for (int i = 0; i < 4; i++)
#pragma unroll
        for (int j = 0; j < 4; j++) {
            int m = m0 + ty + 16 * i;
            int n = n0 + tx + 16 * j;
            out[m * D_ + n] = acc[i][j] + bias[n] + skip[m * D_ + n];
        }
}

// ---------------------------------------------------------------------------
extern "C" void kernel_launch(void* const* d_in, const int* in_sizes, int n_in,
                              void* d_out, int out_size) {
    (void)in_sizes; (void)n_in; (void)out_size;
    const float* in_feats = (const float*)d_in[0];
    const float* wq   = (const float*)d_in[1];
    const float* wk   = (const float*)d_in[2];
    const float* wv   = (const float*)d_in[3];
    const float* fc_w = (const float*)d_in[4];
    const float* fc_b = (const float*)d_in[5];
    const float* ln_w = (const float*)d_in[6];
    const float* ln_b = (const float*)d_in[7];
    float* out = (float*)d_out;

    const int ATTN_SMEM = 4 * 64 * 68 * (int)sizeof(float);  // 69632 B
    cudaFuncSetAttribute(attn_kernel, cudaFuncAttributeMaxDynamicSharedMemorySize, ATTN_SMEM);

    ln_kernel<<<B_, 128>>>(in_feats, ln_w, ln_b);
    qkv_gemm<<<dim3(B_ / 64, D_ / 64, 3), 256>>>(wq, wk, wv);
    attn_kernel<<<dim3(B_ / 64, H_), 256, ATTN_SMEM>>>();
    fc_gemm<<<dim3(B_ / 64, D_ / 64), 256>>>(fc_w, fc_b, in_feats, out);
}

// round 11
// speedup vs baseline: 1.0017x; 1.0017x over previous
#include <cuda_runtime.h>
#include <math.h>

#define B_ 4096
#define D_ 512
#define H_ 8

// Scratch (allocation-free: device globals)
__device__ float g_x[B_ * D_];   // layernormed input
__device__ float g_q[B_ * D_];
__device__ float g_k[B_ * D_];
__device__ float g_v[B_ * D_];
__device__ float g_ao[B_ * D_];  // attention output

// ---------------------------------------------------------------------------
// LayerNorm: one CTA (128 threads) per row of 512 floats (float4 per thread)
// ---------------------------------------------------------------------------
__global__ __launch_bounds__(128) void ln_kernel(const float* __restrict__ in,
                                                 const float* __restrict__ w,
                                                 const float* __restrict__ b) {
    int row = blockIdx.x;
    int t = threadIdx.x;
    float4 v = ((const float4*)(in + row * D_))[t];
    float s  = v.x + v.y + v.z + v.w;
    float sq = v.x * v.x + v.y * v.y + v.z * v.z + v.w * v.w;
#pragma unroll
    for (int d = 16; d > 0; d >>= 1) {
        s  += __shfl_xor_sync(0xffffffffu, s, d);
        sq += __shfl_xor_sync(0xffffffffu, sq, d);
    }
    __shared__ float ss[4], ssq[4];
    if ((t & 31) == 0) { ss[t >> 5] = s; ssq[t >> 5] = sq; }
    __syncthreads();
    s  = ss[0] + ss[1] + ss[2] + ss[3];
    sq = ssq[0] + ssq[1] + ssq[2] + ssq[3];
    float mu   = s * (1.0f / D_);
    float var  = fmaxf(sq * (1.0f / D_) - mu * mu, 0.0f);
    float rstd = rsqrtf(var + 1e-5f);
    float4 wv = ((const float4*)w)[t];
    float4 bv = ((const float4*)b)[t];
    float4 o;
    o.x = (v.x - mu) * rstd * wv.x + bv.x;
    o.y = (v.y - mu) * rstd * wv.y + bv.y;
    o.z = (v.z - mu) * rstd * wv.z + bv.z;
    o.w = (v.w - mu) * rstd * wv.w + bv.w;
    ((float4*)(g_x + row * D_))[t] = o;
}

// ---------------------------------------------------------------------------
// QKV GEMM: C[m,n] = sum_k X[m,k] * W[n,k]   (64x64 tiles, 4x4/thread strided)
// blockIdx.z selects q/k/v
// ---------------------------------------------------------------------------
__global__ __launch_bounds__(256) void qkv_gemm(const float* __restrict__ Wq,
                                                const float* __restrict__ Wk,
                                                const float* __restrict__ Wv) {
    __shared__ float As[64 * 68];
    __shared__ float Bs[64 * 68];
    const float* W = (blockIdx.z == 0) ? Wq : ((blockIdx.z == 1) ? Wk : Wv);
    float* C = (blockIdx.z == 0) ? g_q : ((blockIdx.z == 1) ? g_k : g_v);
    int tid = threadIdx.x;
    int ty = tid >> 4, tx = tid & 15;
    int m0 = blockIdx.x * 64, n0 = blockIdx.y * 64;
    int lr = tid >> 4, lc = (tid & 15) * 4;
    float acc[4][4] = {};
    for (int k0 = 0; k0 < D_; k0 += 64) {
#pragma unroll
        for (int r = 0; r < 64; r += 16) {
            *(float4*)&As[(lr + r) * 68 + lc] = *(const float4*)&g_x[(m0 + lr + r) * D_ + k0 + lc];
            *(float4*)&Bs[(lr + r) * 68 + lc] = *(const float4*)&W[(n0 + lr + r) * D_ + k0 + lc];
        }
        __syncthreads();
#pragma unroll 16
        for (int kk = 0; kk < 64; kk++) {
            float a[4], b[4];
#pragma unroll
            for (int i = 0; i < 4; i++) a[i] = As[(ty + 16 * i) * 68 + kk];
#pragma unroll
            for (int j = 0; j < 4; j++) b[j] = Bs[(tx + 16 * j) * 68 + kk];
#pragma unroll
            for (int i = 0; i < 4; i++)
#pragma unroll
                for (int j = 0; j < 4; j++) acc[i][j] += a[i] * b[j];
        }
        __syncthreads();
    }
#pragma unroll
    for (int i = 0; i < 4; i++)
#pragma unroll
        for (int j = 0; j < 4; j++)
            C[(m0 + ty + 16 * i) * D_ + n0 + tx + 16 * j] = acc[i][j];
}

// ---------------------------------------------------------------------------
// Flash attention, fp32, per (64-query-block, head). BM=BN=DH=64.
// S = (Q K^T)/sqrt(512); leaky_relu(0.2); online softmax; O += P V.
// ---------------------------------------------------------------------------
__global__ __launch_bounds__(256) void attn_kernel() {
    extern __shared__ float smbuf[];
    float* Qs = smbuf;                 // [64][68]
    float* Ks = smbuf + 64 * 68;
    float* Vs = smbuf + 2 * 64 * 68;
    float* Ps = smbuf + 3 * 64 * 68;
    int h  = blockIdx.y;
    int m0 = blockIdx.x * 64;
    int tid = threadIdx.x;
    int ty = tid >> 4, tx = tid & 15;
    int lr = tid >> 4, lc = (tid & 15) * 4;
    const float invt = 0.044194173824159216f;  // 1/sqrt(512)

#pragma unroll
    for (int r = 0; r < 64; r += 16) {
        float4 q = *(const float4*)&g_q[(m0 + lr + r) * D_ + h * 64 + lc];
        q.x *= invt; q.y *= invt; q.z *= invt; q.w *= invt;
        *(float4*)&Qs[(lr + r) * 68 + lc] = q;
    }

    float m_i[4], l_i[4], o[4][4];
#pragma unroll
    for (int i = 0; i < 4; i++) {
        m_i[i] = -1e30f; l_i[i] = 0.0f;
#pragma unroll
        for (int j = 0; j < 4; j++) o[i][j] = 0.0f;
    }

    for (int nb = 0; nb < 64; nb++) {
        int n0 = nb * 64;
#pragma unroll
        for (int r = 0; r < 64; r += 16) {
            *(float4*)&Ks[(lr + r) * 68 + lc] = *(const float4*)&g_k[(n0 + lr + r) * D_ + h * 64 + lc];
            *(float4*)&Vs[(lr + r) * 68 + lc] = *(const float4*)&g_v[(n0 + lr + r) * D_ + h * 64 + lc];
        }
        __syncthreads();

        float s[4][4] = {};
#pragma unroll 16
        for (int kk = 0; kk < 64; kk++) {
            float a[4], b[4];
#pragma unroll
            for (int i = 0; i < 4; i++) a[i] = Qs[(ty + 16 * i) * 68 + kk];
#pragma unroll
            for (int j = 0; j < 4; j++) b[j] = Ks[(tx + 16 * j) * 68 + kk];
#pragma unroll
            for (int i = 0; i < 4; i++)
#pragma unroll
                for (int j = 0; j < 4; j++) s[i][j] += a[i] * b[j];
        }
        // leaky relu (scale 1/temp already folded into Q)
#pragma unroll
        for (int i = 0; i < 4; i++)
#pragma unroll
            for (int j = 0; j < 4; j++) {
                float z = s[i][j];
                s[i][j] = (z >= 0.0f) ? z : 0.2f * z;
            }
        // row max across the 16 tx-threads (lanes 0-15 / 16-31 of warp)
        float rm[4], alpha[4], rs[4];
#pragma unroll
        for (int i = 0; i < 4; i++)
            rm[i] = fmaxf(fmaxf(s[i][0], s[i][1]), fmaxf(s[i][2], s[i][3]));
#pragma unroll
        for (int d = 8; d > 0; d >>= 1)
#pragma unroll
            for (int i = 0; i < 4; i++)
                rm[i] = fmaxf(rm[i], __shfl_xor_sync(0xffffffffu, rm[i], d, 16));
#pragma unroll
        for (int i = 0; i < 4; i++) {
            float mn = fmaxf(m_i[i], rm[i]);
            alpha[i] = __expf(m_i[i] - mn);
            m_i[i] = mn;
            rs[i] = 0.0f;
        }
#pragma unroll
        for (int i = 0; i < 4; i++)
#pragma unroll
            for (int j = 0; j < 4; j++) {
                float p = __expf(s[i][j] - m_i[i]);
                Ps[(ty + 16 * i) * 68 + tx + 16 * j] = p;
                rs[i] += p;
            }
#pragma unroll
        for (int d = 8; d > 0; d >>= 1)
#pragma unroll
            for (int i = 0; i < 4; i++)
                rs[i] += __shfl_xor_sync(0xffffffffu, rs[i], d, 16);
#pragma unroll
        for (int i = 0; i < 4; i++) {
            l_i[i] = l_i[i] * alpha[i] + rs[i];
#pragma unroll
            for (int j = 0; j < 4; j++) o[i][j] *= alpha[i];
        }
        __syncthreads();  // Ps visible

#pragma unroll 16
        for (int kk = 0; kk < 64; kk++) {
            float p[4], vv[4];
#pragma unroll
            for (int i = 0; i < 4; i++) p[i] = Ps[(ty + 16 * i) * 68 + kk];
#pragma unroll
            for (int j = 0; j < 4; j++) vv[j] = Vs[kk * 68 + tx + 16 * j];
#pragma unroll
            for (int i = 0; i < 4; i++)
#pragma unroll
                for (int j = 0; j < 4; j++) o[i][j] += p[i] * vv[j];
        }
        __syncthreads();  // done with Ks/Vs/Ps before next-iter overwrite
    }

#pragma unroll
    for (int i = 0; i < 4; i++) {
        float inv = 1.0f / l_i[i];
#pragma unroll
        for (int j = 0; j < 4; j++)
            g_ao[(m0 + ty + 16 * i) * D_ + h * 64 + tx + 16 * j] = o[i][j] * inv;
    }
}

// ---------------------------------------------------------------------------
// FC GEMM + bias + residual: out = g_ao @ fc_w^T + fc_b + in_feats
// ---------------------------------------------------------------------------
__global__ __launch_bounds__(256) void fc_gemm(const float* __restrict__ W,
                                               const float* __restrict__ bias,
                                               const float* __restrict__ skip,
                                               float* __restrict__ out) {
    __shared__ float As[64 * 68];
    __shared__ float Bs[64 * 68];
    int tid = threadIdx.x;
    int ty = tid >> 4, tx = tid & 15;
    int m0 = blockIdx.x * 64, n0 = blockIdx.y * 64;
    int lr = tid >> 4, lc = (tid & 15) * 4;
    float acc[4][4] = {};
    for (int k0 = 0; k0 < D_; k0 += 64) {
#pragma unroll
        for (int r = 0; r < 64; r += 16) {
            *(float4*)&As[(lr + r) * 68 + lc] = *(const float4*)&g_ao[(m0 + lr + r) * D_ + k0 + lc];
            *(float4*)&Bs[(lr + r) * 68 + lc] = *(const float4*)&W[(n0 + lr + r) * D_ + k0 + lc];
        }
        __syncthreads();
#pragma unroll 16
        for (int kk = 0; kk < 64; kk++) {
            float a[4], b[4];
#pragma unroll
            for (int i = 0; i < 4; i++) a[i] = As[(ty + 16 * i) * 68 + kk];
#pragma unroll
            for (int j = 0; j < 4; j++) b[j] = Bs[(tx + 16 * j) * 68 + kk];
#pragma unroll
            for (int i = 0; i < 4; i++)
#pragma unroll
                for (int j = 0; j < 4; j++) acc[i][j] += a[i] * b[j];
        }
        __syncthreads();
    }
#pragma unroll
    for (int i = 0; i < 4; i++)
#pragma unroll
        for (int j = 0; j < 4; j++) {
            int m = m0 + ty + 16 * i;
            int n = n0 + tx + 16 * j;
            out[m * D_ + n] = acc[i][j] + bias[n] + skip[m * D_ + n];
        }
}

// ---------------------------------------------------------------------------
extern "C" void kernel_launch(void* const* d_in, const int* in_sizes, int n_in,
                              void* d_out, int out_size) {
    (void)in_sizes; (void)n_in; (void)out_size;
    const float* in_feats = (const float*)d_in[0];
    const float* wq   = (const float*)d_in[1];
    const float* wk   = (const float*)d_in[2];
    const float* wv   = (const float*)d_in[3];
    const float* fc_w = (const float*)d_in[4];
    const float* fc_b = (const float*)d_in[5];
    const float* ln_w = (const float*)d_in[6];
    const float* ln_b = (const float*)d_in[7];
    float* out = (float*)d_out;

    const int ATTN_SMEM = 4 * 64 * 68 * (int)sizeof(float);  // 69632 B
    cudaFuncSetAttribute(attn_kernel, cudaFuncAttributeMaxDynamicSharedMemorySize, ATTN_SMEM);

    ln_kernel<<<B_, 128>>>(in_feats, ln_w, ln_b);
    qkv_gemm<<<dim3(B_ / 64, D_ / 64, 3), 256>>>(wq, wk, wv);
    attn_kernel<<<dim3(B_ / 64, H_), 256, ATTN_SMEM>>>();
    fc_gemm<<<dim3(B_ / 64, D_ / 64), 256>>>(fc_w, fc_b, in_feats, out);
}